// round 10
// baseline (speedup 1.0000x reference)
#include <cuda_runtime.h>
#include <stdint.h>
#include <math.h>

#define NCAND  1600
#define NITER  100
#define NZ     16
#define NB     524288               // 2^19 bins (R4-proven)
#define CHUNK  1024
#define NCHUNK (NB / CHUNK)         // 512
#define MMGRID 512

#define FIXS    68719476736.0       // 2^36 (double)
#define INVFIXS (1.0 / 68719476736.0)

typedef unsigned long long u64;
typedef long long          s64;
typedef unsigned           u32;

// ---------------- device scratch ----------------
__device__ float g_bmin[MMGRID], g_bmax[MMGRID];
__device__ float g_xminf, g_xmaxf, g_invwf;
__device__ float g_sc[NCAND], g_ql[NCAND];
__device__ float g_newmin[NCAND], g_newmax[NCAND];
__device__ u32   g_cnt[NB];
__device__ u64   g_sum[NB];
__device__ u32   g_pc[NB + 1];      // chunk-relative exclusive prefix counts
__device__ u64   g_ps[NB + 1];      // chunk-relative exclusive prefix sums
__device__ u32   g_ccnt[NCHUNK];
__device__ u64   g_csum[NCHUNK];

// ---------------- pass A: per-block min/max + clear hist arrays ---------------
__global__ void minmax_clear_kernel(const float4* __restrict__ x4, int n4) {
    int stride = gridDim.x * blockDim.x;
    int tid0 = blockIdx.x * blockDim.x + threadIdx.x;

    for (int i = tid0; i < NB; i += stride) { g_cnt[i] = 0u; g_sum[i] = 0ull; }

    float lmin = 3.4e38f, lmax = -3.4e38f;
    for (int i = tid0; i < n4; i += stride) {
        float4 v = x4[i];
        lmin = fminf(lmin, fminf(fminf(v.x, v.y), fminf(v.z, v.w)));
        lmax = fmaxf(lmax, fmaxf(fmaxf(v.x, v.y), fmaxf(v.z, v.w)));
    }
    #pragma unroll
    for (int o = 16; o; o >>= 1) {
        lmin = fminf(lmin, __shfl_xor_sync(0xffffffffu, lmin, o));
        lmax = fmaxf(lmax, __shfl_xor_sync(0xffffffffu, lmax, o));
    }
    __shared__ float smin[8], smax[8];
    int w = threadIdx.x >> 5;
    if ((threadIdx.x & 31) == 0) { smin[w] = lmin; smax[w] = lmax; }
    __syncthreads();
    if (threadIdx.x == 0) {
        for (int i = 1; i < (int)(blockDim.x >> 5); i++) {
            lmin = fminf(lmin, smin[i]);
            lmax = fmaxf(lmax, smax[i]);
        }
        g_bmin[blockIdx.x] = lmin;
        g_bmax[blockIdx.x] = lmax;
    }
}

// ---------------- pass B: finish min/max + candidate params -------------------
__global__ void __launch_bounds__(512) cand_kernel() {
    __shared__ float smn[512], smx[512];
    int t = threadIdx.x;
    smn[t] = g_bmin[t];              // MMGRID == 512
    smx[t] = g_bmax[t];
    __syncthreads();
    for (int off = 256; off; off >>= 1) {
        if (t < off) {
            smn[t] = fminf(smn[t], smn[t + off]);
            smx[t] = fmaxf(smx[t], smx[t + off]);
        }
        __syncthreads();
    }
    const float x_min = smn[0];
    const float x_max = smx[0];
    const float xrange = x_max - x_min;
    if (t == 0) {
        g_xminf = x_min;
        g_xmaxf = x_max;
        g_invwf = (float)NB / xrange;
    }
    const float EPS = 1.1920929e-7f;  // np.finfo(float32).eps
    for (int c = t; c < NCAND; c += 512) {
        int i = c / NZ + 1;
        int z = c % NZ;
        float fi = (float)i, fz = (float)z;
        float tmp_max   = xrange / 100.0f * fi;
        float tmp_delta = tmp_max / 15.0f;
        float new_min = fmaxf(-fz * tmp_delta, x_min);
        float new_max = fminf(tmp_max - fz * tmp_delta, x_max);
        float min_neg = fminf(new_min, 0.0f);
        float max_pos = fmaxf(new_max, 0.0f);
        float scale = fmaxf((max_pos - min_neg) / 15.0f, EPS);
        float zp = fminf(fmaxf(0.0f - rintf(min_neg / scale), 0.0f), 15.0f);
        g_sc[c] = scale;
        g_ql[c] = -zp;
        g_newmin[c] = new_min;
        g_newmax[c] = new_max;
    }
}

// ---------------- pass C: histogram — VERBATIM R4 (measured 45.4 us) ----------
__global__ void hist_kernel(const float4* __restrict__ x4, int n4) {
    const float xminf = g_xminf;
    const float invwf = g_invwf;
    for (int i = blockIdx.x * blockDim.x + threadIdx.x; i < n4;
         i += gridDim.x * blockDim.x) {
        float4 v = x4[i];
        float f[4] = {v.x, v.y, v.z, v.w};
        #pragma unroll
        for (int k = 0; k < 4; k++) {
            float d = f[k] - xminf;
            int b = (int)(d * invwf);
            b = min(max(b, 0), NB - 1);
            double dd = (double)f[k] - (double)xminf;   // exact
            u64 fx = (u64)(long long)llrint(dd * FIXS);
            atomicAdd(&g_cnt[b], 1u);
            atomicAdd(&g_sum[b], fx);
        }
    }
}

// ---------------- pass D: per-chunk scan (block b <-> chunk b) ----------------
__global__ void __launch_bounds__(CHUNK) scan_kernel() {
    __shared__ u32 sc[CHUNK];
    __shared__ u64 ss[CHUNK];
    int b = blockIdx.x, t = threadIdx.x;
    int i = b * CHUNK + t;
    u32 v = g_cnt[i];
    u64 w = g_sum[i];
    sc[t] = v; ss[t] = w; __syncthreads();
    for (int off = 1; off < CHUNK; off <<= 1) {
        u32 a = 0; u64 a2 = 0;
        if (t >= off) { a = sc[t - off]; a2 = ss[t - off]; }
        __syncthreads();
        sc[t] += a; ss[t] += a2;
        __syncthreads();
    }
    g_pc[i] = sc[t] - v;                 // chunk-relative exclusive
    g_ps[i] = ss[t] - w;
    if (t == CHUNK - 1) {
        g_ccnt[b] = sc[t];
        g_csum[b] = ss[t];
        if (b == NCHUNK - 1) { g_pc[NB] = 0u; g_ps[NB] = 0ull; }
    }
}

// ---------------- pass E: chunk prefix + scores + reference-exact select ------
__device__ __forceinline__ int gidx(float E, float xminf, float invwf) {
    float t = (E - xminf) * invwf;
    if (!(t > 0.0f)) return 0;
    if (t >= (float)NB) return NB;
    return (int)t;
}

__global__ void __launch_bounds__(1024) finish_kernel(float* __restrict__ out,
                                                      int ntot) {
    __shared__ u32    s_cc[NCHUNK];
    __shared__ u64    s_cs[NCHUNK];
    __shared__ u32    s_cpref[NCHUNK + 1];
    __shared__ u64    s_spref[NCHUNK + 1];
    __shared__ double s_score[NCAND];
    __shared__ double sm_i[NITER];
    __shared__ int    j_i[NITER];
    int t = threadIdx.x;

    if (t < NCHUNK) { s_cc[t] = g_ccnt[t]; s_cs[t] = g_csum[t]; }
    __syncthreads();
    for (int off = 1; off < NCHUNK; off <<= 1) {   // inclusive scan over 512
        u32 a = 0; u64 a2 = 0;
        if (t < NCHUNK && t >= off) { a = s_cc[t - off]; a2 = s_cs[t - off]; }
        __syncthreads();
        if (t < NCHUNK) { s_cc[t] += a; s_cs[t] += a2; }
        __syncthreads();
    }
    if (t <= NCHUNK) {
        s_cpref[t] = (t == 0) ? 0u   : s_cc[t - 1];
        s_spref[t] = (t == 0) ? 0ull : s_cs[t - 1];
    }
    __syncthreads();

    const float xminf = g_xminf;
    const float invwf = g_invwf;
    const double xmind = (double)xminf;

    for (int c = t; c < NCAND; c += 1024) {
        float s  = g_sc[c];
        float ql = g_ql[c];
        int e[NZ + 1];
        e[0] = 0; e[NZ] = NB;
        #pragma unroll
        for (int m = 0; m < NZ - 1; m++)
            e[m + 1] = gidx((ql + (float)m + 0.5f) * s, xminf, invwf);
        #pragma unroll
        for (int m = 1; m < NZ; m++) if (e[m] < e[m - 1]) e[m] = e[m - 1];
        double num = 0.0;
        #pragma unroll
        for (int m = 0; m < NZ; m++) {
            int e0 = e[m], e1 = e[m + 1];
            u32 pc0 = s_cpref[e0 >> 10] + g_pc[e0];
            u32 pc1 = s_cpref[e1 >> 10] + g_pc[e1];
            u64 ps0 = s_spref[e0 >> 10] + g_ps[e0];
            u64 ps1 = s_spref[e1 >> 10] + g_ps[e1];
            double Nm = (double)(pc1 - pc0);
            double S1 = (double)(s64)(ps1 - ps0) * INVFIXS + Nm * xmind;
            float a = (ql + (float)m) * s;
            double ad = (double)a;
            num += ad * ad * Nm - 2.0 * ad * S1;
        }
        s_score[c] = num / (double)ntot;     // Σx² omitted: constant offset
    }
    __syncthreads();

    if (t < NITER) {
        int j = 0;
        double sm = s_score[t * NZ];
        #pragma unroll
        for (int z = 1; z < NZ; z++) {
            double s = s_score[t * NZ + z];
            if (s < sm) { sm = s; j = z; }   // first-occurrence argmin
        }
        sm_i[t] = sm; j_i[t] = j;
    }
    __syncthreads();
    if (t == 0) {
        double best = 1e30;
        float bmin = g_xminf, bmax = g_xmaxf;
        for (int i = 0; i < NITER; i++) {
            if (sm_i[i] < best) {            // strict <, like reference
                best = sm_i[i];
                bmin = g_newmin[i * NZ + j_i[i]];
                bmax = g_newmax[i * NZ + j_i[i]];
            }
        }
        out[0] = bmin;
        out[1] = bmax;
    }
}

extern "C" void kernel_launch(void* const* d_in, const int* in_sizes, int n_in,
                              void* d_out, int out_size) {
    const float* x = (const float*)d_in[0];
    int n = in_sizes[0];
    int n4 = n / 4;

    minmax_clear_kernel<<<MMGRID, 256>>>((const float4*)x, n4);
    cand_kernel<<<1, 512>>>();
    hist_kernel<<<2048, 256>>>((const float4*)x, n4);
    scan_kernel<<<NCHUNK, CHUNK>>>();
    finish_kernel<<<1, 1024>>>((float*)d_out, n);
}

// round 11
// speedup vs baseline: 1.0436x; 1.0436x over previous
#include <cuda_runtime.h>
#include <stdint.h>

#define NCAND  1600
#define NITER  100
#define NZ     16
#define NB     65536               // 2^16 bins
#define FRAC   7                   // sub-bin bits; NB<<FRAC = 2^23
#define NCHUNK 256
#define CHUNK  256                 // NB / NCHUNK
#define GRID   296                 // 2 blocks/SM * 148 SMs
#define BLK    1024

#define MAGICF 8388608.0f          // 2^23
#define HIF    16777215.0f         // 2^24 - 1
#define OVF    16777216.0f         // 2^24

typedef unsigned long long u64;
typedef long long          s64;
typedef unsigned           u32;

// ---------------- device scratch ----------------
__device__ u32    g_ctr;           // barrier counter; reset by block 0 at end
__device__ float  g_bmin[GRID], g_bmax[GRID];
__device__ u64    g_hist[NB];      // (count << 32) | sum_of_7bit_offsets
__device__ u32    g_pc[NB + 1];    // chunk-relative exclusive prefix counts
__device__ u64    g_ps[NB + 1];    // chunk-relative exclusive prefix units
__device__ u32    g_ccnt[NCHUNK];
__device__ u64    g_csum[NCHUNK];
__device__ double g_score[NCAND];

__device__ __forceinline__ void gbar_full(u32 k) {
    __syncthreads();
    if (threadIdx.x == 0) {
        __threadfence();
        atomicAdd(&g_ctr, 1u);
        u32 target = k * (u32)GRID;
        while ((int)(*(volatile u32*)&g_ctr - target) < 0) __nanosleep(64);
        __threadfence();
    }
    __syncthreads();
}

__global__ void __launch_bounds__(BLK, 2)      // forces <=32 regs -> 64 warps/SM
fused_kernel(const float4* __restrict__ x4, int n4, int ntot,
             float* __restrict__ out)
{
    const int tid  = threadIdx.x;
    const int bid  = blockIdx.x;
    const int gtid = bid * BLK + tid;
    const int gsz  = GRID * BLK;

    __shared__ float  s_mn[32], s_mx[32];
    __shared__ float  s_rm[512], s_rx[512];
    __shared__ float  sb_xmin, sb_xmax, sb_C1, sb_C2;
    __shared__ u32    s_c[CHUNK];
    __shared__ u64    s_s[CHUNK];
    __shared__ u32    s_cc[NCHUNK];
    __shared__ u64    s_cs[NCHUNK];
    __shared__ u32    s_cpref[NCHUNK + 1];
    __shared__ u64    s_spref[NCHUNK + 1];
    __shared__ double sm_i[NITER];
    __shared__ int    j_i[NITER];

    // ---------------- P0: clear hist + per-block min/max -----------------
    if (gtid < NB) g_hist[gtid] = 0ull;        // NB < GRID*BLK

    float lmin = 3.4e38f, lmax = -3.4e38f;
    for (int i = gtid; i < n4; i += gsz) {
        float4 v = __ldg(&x4[i]);
        lmin = fminf(lmin, fminf(fminf(v.x, v.y), fminf(v.z, v.w)));
        lmax = fmaxf(lmax, fmaxf(fmaxf(v.x, v.y), fmaxf(v.z, v.w)));
    }
    #pragma unroll
    for (int o = 16; o; o >>= 1) {
        lmin = fminf(lmin, __shfl_xor_sync(0xffffffffu, lmin, o));
        lmax = fmaxf(lmax, __shfl_xor_sync(0xffffffffu, lmax, o));
    }
    if ((tid & 31) == 0) { s_mn[tid >> 5] = lmin; s_mx[tid >> 5] = lmax; }
    __syncthreads();
    if (tid == 0) {
        #pragma unroll
        for (int i = 1; i < 32; i++) {
            lmin = fminf(lmin, s_mn[i]);
            lmax = fmaxf(lmax, s_mx[i]);
        }
        g_bmin[bid] = lmin;
        g_bmax[bid] = lmax;
    }
    gbar_full(1);

    // ------- P1: every block reduces the 296 partials identically --------
    if (tid < 512) {
        s_rm[tid] = (tid < GRID) ? __ldcg(&g_bmin[tid]) :  3.4e38f;
        s_rx[tid] = (tid < GRID) ? __ldcg(&g_bmax[tid]) : -3.4e38f;
    }
    __syncthreads();
    for (int off = 256; off; off >>= 1) {
        if (tid < off) {
            s_rm[tid] = fminf(s_rm[tid], s_rm[tid + off]);
            s_rx[tid] = fmaxf(s_rx[tid], s_rx[tid + off]);
        }
        __syncthreads();
    }
    if (tid == 0) {
        float xmin = s_rm[0], xmax = s_rx[0];
        float xr = xmax - xmin;
        float C1 = MAGICF / xr;
        sb_xmin = xmin; sb_xmax = xmax;
        sb_C1 = C1;
        sb_C2 = MAGICF - xmin * C1;
    }
    __syncthreads();
    const float C1 = sb_C1;
    const float C2 = sb_C2;

    // ------- P1b: histogram, 1 u64 atomic per element, 64 warps/SM -------
    for (int i = gtid; i < n4; i += gsz) {
        float4 v = __ldg(&x4[i]);
        float t0 = fminf(fmaxf(fmaf(v.x, C1, C2), MAGICF), HIF);
        float t1 = fminf(fmaxf(fmaf(v.y, C1, C2), MAGICF), HIF);
        float t2 = fminf(fmaxf(fmaf(v.z, C1, C2), MAGICF), HIF);
        float t3 = fminf(fmaxf(fmaf(v.w, C1, C2), MAGICF), HIF);
        u32 q0 = __float_as_uint(t0) - 0x4B000000u;
        u32 q1 = __float_as_uint(t1) - 0x4B000000u;
        u32 q2 = __float_as_uint(t2) - 0x4B000000u;
        u32 q3 = __float_as_uint(t3) - 0x4B000000u;
        atomicAdd(&g_hist[q0 >> FRAC], (1ull << 32) + (u64)(q0 & 127u));
        atomicAdd(&g_hist[q1 >> FRAC], (1ull << 32) + (u64)(q1 & 127u));
        atomicAdd(&g_hist[q2 >> FRAC], (1ull << 32) + (u64)(q2 & 127u));
        atomicAdd(&g_hist[q3 >> FRAC], (1ull << 32) + (u64)(q3 & 127u));
    }
    gbar_full(2);

    // ---------------- P2: per-chunk scan (blocks 0..255) -----------------
    if (bid < NCHUNK) {
        int i = bid * CHUNK + tid;
        u32 v = 0; u64 w = 0;
        if (tid < CHUNK) {
            u64 p = __ldcg(&g_hist[i]);
            v = (u32)(p >> 32);
            w = ((u64)v * (u64)i << FRAC) + (p & 0xFFFFFFFFull);
            s_c[tid] = v; s_s[tid] = w;
        }
        __syncthreads();
        for (int off = 1; off < CHUNK; off <<= 1) {
            u32 a = 0; u64 a2 = 0;
            if (tid < CHUNK && tid >= off) { a = s_c[tid - off]; a2 = s_s[tid - off]; }
            __syncthreads();
            if (tid < CHUNK) { s_c[tid] += a; s_s[tid] += a2; }
            __syncthreads();
        }
        if (tid < CHUNK) {
            g_pc[i] = s_c[tid] - v;            // chunk-relative exclusive
            g_ps[i] = s_s[tid] - w;
        }
        if (tid == CHUNK - 1) {
            g_ccnt[bid] = s_c[tid];
            g_csum[bid] = s_s[tid];
        }
        if (bid == NCHUNK - 1 && tid == 0) { g_pc[NB] = 0u; g_ps[NB] = 0ull; }
    }

    // ---------------- P3: arrive-only for blocks != 0 --------------------
    __syncthreads();
    if (bid != 0) {
        if (tid == 0) { __threadfence(); atomicAdd(&g_ctr, 1u); }
        return;
    }
    if (tid == 0) {
        __threadfence();
        atomicAdd(&g_ctr, 1u);
        while ((int)(*(volatile u32*)&g_ctr - 3u * GRID) < 0) __nanosleep(64);
        __threadfence();
    }
    __syncthreads();

    // ------- P4 (block 0): chunk prefix + scores + exact select ----------
    if (tid < NCHUNK) {
        s_cc[tid] = __ldcg(&g_ccnt[tid]);
        s_cs[tid] = __ldcg(&g_csum[tid]);
    }
    __syncthreads();
    for (int off = 1; off < NCHUNK; off <<= 1) {   // inclusive scan, 256 wide
        u32 a = 0; u64 a2 = 0;
        if (tid < NCHUNK && tid >= off) { a = s_cc[tid - off]; a2 = s_cs[tid - off]; }
        __syncthreads();
        if (tid < NCHUNK) { s_cc[tid] += a; s_cs[tid] += a2; }
        __syncthreads();
    }
    if (tid <= NCHUNK) {
        s_cpref[tid] = (tid == 0) ? 0u   : s_cc[tid - 1];
        s_spref[tid] = (tid == 0) ? 0ull : s_cs[tid - 1];
    }
    __syncthreads();

    const float x_min = sb_xmin;
    const float x_max = sb_xmax;
    const float xrange = x_max - x_min;
    const double xmind = (double)x_min;
    const double UPQ = (double)xrange / 8388608.0;   // x per q-unit
    const float EPS = 1.1920929e-7f;                 // np.finfo(float32).eps

    for (int c = tid; c < NCAND; c += BLK) {
        int ii = c / NZ + 1;
        int z  = c % NZ;
        float fi = (float)ii, fz = (float)z;
        float tmp_max   = xrange / 100.0f * fi;
        float tmp_delta = tmp_max / 15.0f;
        float new_min = fmaxf(-fz * tmp_delta, x_min);
        float new_max = fminf(tmp_max - fz * tmp_delta, x_max);
        float min_neg = fminf(new_min, 0.0f);
        float max_pos = fmaxf(new_max, 0.0f);
        float scale = fmaxf((max_pos - min_neg) / 15.0f, EPS);
        float zp = fminf(fmaxf(0.0f - rintf(min_neg / scale), 0.0f), 15.0f);
        float ql = -zp;

        int e[NZ + 1];
        e[0] = 0; e[NZ] = NB;
        #pragma unroll
        for (int m = 0; m < NZ - 1; m++) {
            float tr = fmaf((ql + (float)m + 0.5f) * scale, C1, C2);
            int ei;
            if (!(tr > MAGICF))      ei = 0;
            else if (tr >= OVF)      ei = NB;
            else ei = (int)((__float_as_uint(tr) - 0x4B000000u) >> FRAC);
            e[m + 1] = ei;
        }
        #pragma unroll
        for (int m = 1; m < NZ; m++) if (e[m] < e[m - 1]) e[m] = e[m - 1];

        double num = 0.0;
        #pragma unroll
        for (int m = 0; m < NZ; m++) {
            int e0 = e[m], e1 = e[m + 1];
            u32 pc0 = s_cpref[e0 >> 8] + __ldcg(&g_pc[e0]);
            u32 pc1 = s_cpref[e1 >> 8] + __ldcg(&g_pc[e1]);
            u64 ps0 = s_spref[e0 >> 8] + __ldcg(&g_ps[e0]);
            u64 ps1 = s_spref[e1 >> 8] + __ldcg(&g_ps[e1]);
            double Nm = (double)(pc1 - pc0);
            double S1 = (double)(s64)(ps1 - ps0) * UPQ + Nm * xmind;
            float a = (ql + (float)m) * scale;
            double ad = (double)a;
            num += ad * ad * Nm - 2.0 * ad * S1;
        }
        g_score[c] = num / (double)ntot;       // Σx² omitted: constant offset
    }
    __syncthreads();

    if (tid < NITER) {
        int j = 0;
        double sm = g_score[tid * NZ];
        #pragma unroll
        for (int z = 1; z < NZ; z++) {
            double s = g_score[tid * NZ + z];
            if (s < sm) { sm = s; j = z; }     // first-occurrence argmin
        }
        sm_i[tid] = sm; j_i[tid] = j;
    }
    __syncthreads();
    if (tid == 0) {
        double best = 1e30;
        float bmin = x_min, bmax = x_max;
        for (int i = 0; i < NITER; i++) {
            if (sm_i[i] < best) {              // strict <, like reference
                best = sm_i[i];
                int ii = i + 1, z = j_i[i];
                float tmp_max   = xrange / 100.0f * (float)ii;
                float tmp_delta = tmp_max / 15.0f;
                bmin = fmaxf(-(float)z * tmp_delta, x_min);
                bmax = fminf(tmp_max - (float)z * tmp_delta, x_max);
            }
        }
        out[0] = bmin;
        out[1] = bmax;
        atomicExch(&g_ctr, 0u);                // reset for next graph replay
    }
}

extern "C" void kernel_launch(void* const* d_in, const int* in_sizes, int n_in,
                              void* d_out, int out_size) {
    const float* x = (const float*)d_in[0];
    int n = in_sizes[0];
    fused_kernel<<<GRID, BLK>>>((const float4*)x, n / 4, n, (float*)d_out);
}

// round 12
// speedup vs baseline: 1.3866x; 1.3287x over previous
#include <cuda_runtime.h>
#include <stdint.h>

#define NCAND  1600
#define NITER  100
#define NZ     16
#define NB     524288          // histogram bins (2^19)
#define CHUNK  1024
#define NCHUNK (NB / CHUNK)    // 512
#define MMGRID 512

typedef unsigned long long u64;
typedef unsigned u32;

#define FIXS    68719476736.0   // 2^36
#define INVFIXS (1.0 / 68719476736.0)

__device__ u32    g_min_enc;
__device__ u32    g_max_enc;
__device__ float  g_xminf;
__device__ float  g_invwf;
__device__ double g_S2tot;
__device__ double g_s2blk[MMGRID];
__device__ float  g_sc[NCAND];
__device__ float  g_ql[NCAND];
__device__ float  g_newmin[NCAND];
__device__ float  g_newmax[NCAND];
__device__ double g_score[NCAND];
__device__ u32    g_cnt[NB];
__device__ u64    g_sum[NB];
__device__ u32    g_pc[NB + 1];
__device__ u64    g_ps[NB + 1];
__device__ u32    g_ccnt[NCHUNK];
__device__ u64    g_csum[NCHUNK];

__device__ __forceinline__ u32 enc_f(float f) {
    u32 u = __float_as_uint(f);
    return (u & 0x80000000u) ? ~u : (u | 0x80000000u);
}
__device__ __forceinline__ float dec_f(u32 e) {
    return (e & 0x80000000u) ? __uint_as_float(e & 0x7fffffffu)
                             : __uint_as_float(~e);
}

__global__ void clear_kernel() {
    int i = blockIdx.x * blockDim.x + threadIdx.x;
    if (i < NB) { g_cnt[i] = 0u; g_sum[i] = 0ull; }
    if (i == 0) { g_min_enc = 0xFFFFFFFFu; g_max_enc = 0u; }
}

__global__ void minmax_s2_kernel(const float4* __restrict__ x4, int n4) {
    float lmin = 3.4e38f, lmax = -3.4e38f;
    double s2 = 0.0;
    for (int i = blockIdx.x * blockDim.x + threadIdx.x; i < n4;
         i += gridDim.x * blockDim.x) {
        float4 v = x4[i];
        lmin = fminf(lmin, fminf(fminf(v.x, v.y), fminf(v.z, v.w)));
        lmax = fmaxf(lmax, fmaxf(fmaxf(v.x, v.y), fmaxf(v.z, v.w)));
        s2 += (double)v.x * v.x + (double)v.y * v.y
            + (double)v.z * v.z + (double)v.w * v.w;
    }
    #pragma unroll
    for (int o = 16; o; o >>= 1) {
        lmin = fminf(lmin, __shfl_xor_sync(0xffffffffu, lmin, o));
        lmax = fmaxf(lmax, __shfl_xor_sync(0xffffffffu, lmax, o));
        s2  += __shfl_xor_sync(0xffffffffu, s2, o);
    }
    __shared__ float  smin[8], smax[8];
    __shared__ double ss2[8];
    int w = threadIdx.x >> 5;
    if ((threadIdx.x & 31) == 0) { smin[w] = lmin; smax[w] = lmax; ss2[w] = s2; }
    __syncthreads();
    if (threadIdx.x == 0) {
        double b2 = 0.0;
        for (int i = 0; i < (int)(blockDim.x >> 5); i++) {
            lmin = fminf(lmin, smin[i]);
            lmax = fmaxf(lmax, smax[i]);
            b2 += ss2[i];
        }
        atomicMin(&g_min_enc, enc_f(lmin));
        atomicMax(&g_max_enc, enc_f(lmax));
        g_s2blk[blockIdx.x] = b2;
    }
}

__global__ void __launch_bounds__(512) cand_kernel() {
    __shared__ double sd[512];
    int t = threadIdx.x;
    sd[t] = g_s2blk[t];           // MMGRID == 512
    __syncthreads();
    for (int off = 256; off; off >>= 1) {
        if (t < off) sd[t] += sd[t + off];
        __syncthreads();
    }
    const float x_min = dec_f(g_min_enc);
    const float x_max = dec_f(g_max_enc);
    const float xrange = x_max - x_min;
    if (t == 0) {
        g_S2tot = sd[0];
        g_xminf = x_min;
        g_invwf = (float)NB / xrange;
    }
    const float EPS = 1.1920929e-7f;
    for (int c = t; c < NCAND; c += 512) {
        int i = c / NZ + 1;
        int z = c % NZ;
        float fi = (float)i, fz = (float)z;
        float tmp_max   = xrange / 100.0f * fi;
        float tmp_delta = tmp_max / 15.0f;
        float new_min = fmaxf(-fz * tmp_delta, x_min);
        float new_max = fminf(tmp_max - fz * tmp_delta, x_max);
        float min_neg = fminf(new_min, 0.0f);
        float max_pos = fmaxf(new_max, 0.0f);
        float scale = fmaxf((max_pos - min_neg) / 15.0f, EPS);
        float zp = fminf(fmaxf(0.0f - rintf(min_neg / scale), 0.0f), 15.0f);
        g_sc[c] = scale;
        g_ql[c] = -zp;
        g_newmin[c] = new_min;
        g_newmax[c] = new_max;
    }
}

__global__ void hist_kernel(const float4* __restrict__ x4, int n4) {
    const float xminf = g_xminf;
    const float invwf = g_invwf;
    for (int i = blockIdx.x * blockDim.x + threadIdx.x; i < n4;
         i += gridDim.x * blockDim.x) {
        float4 v = x4[i];
        float f[4] = {v.x, v.y, v.z, v.w};
        #pragma unroll
        for (int k = 0; k < 4; k++) {
            float d = f[k] - xminf;
            int b = (int)(d * invwf);
            b = min(max(b, 0), NB - 1);
            double dd = (double)f[k] - (double)xminf;   // exact
            u64 fx = (u64)(long long)llrint(dd * FIXS);
            atomicAdd(&g_cnt[b], 1u);
            atomicAdd(&g_sum[b], fx);
        }
    }
}

__global__ void chunkred_kernel() {
    __shared__ u32 sc[256];
    __shared__ u64 ss[256];
    int b = blockIdx.x, t = threadIdx.x;
    u32 c = 0; u64 s = 0;
    for (int j = t; j < CHUNK; j += 256) {
        c += g_cnt[b * CHUNK + j];
        s += g_sum[b * CHUNK + j];
    }
    sc[t] = c; ss[t] = s; __syncthreads();
    for (int off = 128; off; off >>= 1) {
        if (t < off) { sc[t] += sc[t + off]; ss[t] += ss[t + off]; }
        __syncthreads();
    }
    if (t == 0) { g_ccnt[b] = sc[0]; g_csum[b] = ss[0]; }
}

__global__ void __launch_bounds__(NCHUNK) chunkscan_kernel() {
    __shared__ u32 sc[NCHUNK];
    __shared__ u64 ss[NCHUNK];
    int t = threadIdx.x;
    u32 v = g_ccnt[t];
    u64 w = g_csum[t];
    sc[t] = v; ss[t] = w; __syncthreads();
    for (int off = 1; off < NCHUNK; off <<= 1) {
        u32 a = 0; u64 a2 = 0;
        if (t >= off) { a = sc[t - off]; a2 = ss[t - off]; }
        __syncthreads();
        sc[t] += a; ss[t] += a2;
        __syncthreads();
    }
    g_ccnt[t] = sc[t] - v;   // exclusive
    g_csum[t] = ss[t] - w;
}

__global__ void __launch_bounds__(CHUNK) binscan_kernel() {
    __shared__ u32 sc[CHUNK];
    __shared__ u64 ss[CHUNK];
    int b = blockIdx.x, t = threadIdx.x;
    int i = b * CHUNK + t;
    u32 v = g_cnt[i];
    u64 w = g_sum[i];
    sc[t] = v; ss[t] = w; __syncthreads();
    for (int off = 1; off < CHUNK; off <<= 1) {
        u32 a = 0; u64 a2 = 0;
        if (t >= off) { a = sc[t - off]; a2 = ss[t - off]; }
        __syncthreads();
        sc[t] += a; ss[t] += a2;
        __syncthreads();
    }
    g_pc[i] = g_ccnt[b] + (sc[t] - v);
    g_ps[i] = g_csum[b] + (ss[t] - w);
    if (i == NB - 1) {
        g_pc[NB] = g_ccnt[b] + sc[t];
        g_ps[NB] = g_csum[b] + ss[t];
    }
}

__device__ __forceinline__ int gidx(float E, float xminf, float invwf) {
    float t = (E - xminf) * invwf;
    if (!(t > 0.0f)) return 0;
    if (t >= (float)NB) return NB;
    return (int)t;
}

__global__ void assemble_kernel(int ntot) {
    int c = blockIdx.x * blockDim.x + threadIdx.x;
    if (c >= NCAND) return;
    const float xminf = g_xminf;
    const float invwf = g_invwf;
    const double xmind = (double)xminf;
    float s  = g_sc[c];
    float ql = g_ql[c];
    int e[NZ + 1];
    e[0] = 0; e[NZ] = NB;
    #pragma unroll
    for (int m = 0; m < NZ - 1; m++)
        e[m + 1] = gidx((ql + (float)m + 0.5f) * s, xminf, invwf);
    #pragma unroll
    for (int m = 1; m < NZ; m++) if (e[m] < e[m - 1]) e[m] = e[m - 1];
    double num = 0.0;
    #pragma unroll
    for (int m = 0; m < NZ; m++) {
        u32 pc0 = g_pc[e[m]],  pc1 = g_pc[e[m + 1]];
        u64 ps0 = g_ps[e[m]],  ps1 = g_ps[e[m + 1]];
        double Nm = (double)(pc1 - pc0);
        double S1 = (double)(long long)(ps1 - ps0) * INVFIXS + Nm * xmind;
        float a = (ql + (float)m) * s;
        double ad = (double)a;
        num += ad * ad * Nm - 2.0 * ad * S1;
    }
    g_score[c] = (num + g_S2tot) / (double)ntot;
}

__global__ void __launch_bounds__(128) select_kernel(float* __restrict__ out) {
    __shared__ double sm_i[NITER];
    __shared__ int    j_i[NITER];
    int t = threadIdx.x;
    if (t < NITER) {
        int j = 0;
        double sm = g_score[t * NZ];
        #pragma unroll
        for (int z = 1; z < NZ; z++) {
            double s = g_score[t * NZ + z];
            if (s < sm) { sm = s; j = z; }
        }
        sm_i[t] = sm; j_i[t] = j;
    }
    __syncthreads();
    if (t == 0) {
        double best = 1e30;
        float bmin = dec_f(g_min_enc);
        float bmax = dec_f(g_max_enc);
        for (int i = 0; i < NITER; i++) {
            if (sm_i[i] < best) {
                best = sm_i[i];
                bmin = g_newmin[i * NZ + j_i[i]];
                bmax = g_newmax[i * NZ + j_i[i]];
            }
        }
        out[0] = bmin;
        out[1] = bmax;
    }
}

extern "C" void kernel_launch(void* const* d_in, const int* in_sizes, int n_in,
                              void* d_out, int out_size) {
    const float* x = (const float*)d_in[0];
    int n = in_sizes[0];
    int n4 = n / 4;

    clear_kernel<<<NB / 1024, 1024>>>();
    minmax_s2_kernel<<<MMGRID, 256>>>((const float4*)x, n4);
    cand_kernel<<<1, 512>>>();
    hist_kernel<<<2048, 256>>>((const float4*)x, n4);
    chunkred_kernel<<<NCHUNK, 256>>>();
    chunkscan_kernel<<<1, NCHUNK>>>();
    binscan_kernel<<<NCHUNK, CHUNK>>>();
    assemble_kernel<<<(NCAND + 127) / 128, 128>>>(n);
    select_kernel<<<1, 128>>>((float*)d_out);
}

// round 14
// speedup vs baseline: 1.4966x; 1.0793x over previous
#include <cuda_runtime.h>
#include <stdint.h>

#define NCAND  1600
#define NITER  100
#define NZ     16
#define NB     524288          // histogram bins (2^19)
#define CHUNK  1024
#define NCHUNK (NB / CHUNK)    // 512
#define MMGRID 512

typedef unsigned long long u64;
typedef long long          s64;
typedef unsigned u32;

#define FIXS    68719476736.0   // 2^36
#define INVFIXS (1.0 / 68719476736.0)
#define CNT_SHIFT 44
#define SUM_MASK  ((1ull << CNT_SHIFT) - 1ull)
#define BIASI     ((s64)(1 << 22))

__device__ u32    g_min_enc;
__device__ u32    g_max_enc;
__device__ float  g_xminf;
__device__ float  g_invwf;
__device__ s64    g_W36;
__device__ double g_S2tot;
__device__ double g_s2blk[MMGRID];
__device__ float  g_sc[NCAND];
__device__ float  g_ql[NCAND];
__device__ float  g_newmin[NCAND];
__device__ float  g_newmax[NCAND];
__device__ double g_score[NCAND];
__device__ u64    g_hist[NB];   // (count << 44) | (fx - b*W36 + BIAS)
__device__ u32    g_pc[NB + 1];
__device__ u64    g_ps[NB + 1];
__device__ u32    g_ccnt[NCHUNK];
__device__ u64    g_csum[NCHUNK];

__device__ __forceinline__ u32 enc_f(float f) {
    u32 u = __float_as_uint(f);
    return (u & 0x80000000u) ? ~u : (u | 0x80000000u);
}
__device__ __forceinline__ float dec_f(u32 e) {
    return (e & 0x80000000u) ? __uint_as_float(e & 0x7fffffffu)
                             : __uint_as_float(~e);
}

__global__ void clear_kernel() {
    int i = blockIdx.x * blockDim.x + threadIdx.x;
    if (i < NB) g_hist[i] = 0ull;
    if (i == 0) { g_min_enc = 0xFFFFFFFFu; g_max_enc = 0u; }
}

__global__ void minmax_s2_kernel(const float4* __restrict__ x4, int n4) {
    float lmin = 3.4e38f, lmax = -3.4e38f;
    double s2 = 0.0;
    for (int i = blockIdx.x * blockDim.x + threadIdx.x; i < n4;
         i += gridDim.x * blockDim.x) {
        float4 v = x4[i];
        lmin = fminf(lmin, fminf(fminf(v.x, v.y), fminf(v.z, v.w)));
        lmax = fmaxf(lmax, fmaxf(fmaxf(v.x, v.y), fmaxf(v.z, v.w)));
        s2 += (double)v.x * v.x + (double)v.y * v.y
            + (double)v.z * v.z + (double)v.w * v.w;
    }
    #pragma unroll
    for (int o = 16; o; o >>= 1) {
        lmin = fminf(lmin, __shfl_xor_sync(0xffffffffu, lmin, o));
        lmax = fmaxf(lmax, __shfl_xor_sync(0xffffffffu, lmax, o));
        s2  += __shfl_xor_sync(0xffffffffu, s2, o);
    }
    __shared__ float  smin[8], smax[8];
    __shared__ double ss2[8];
    int w = threadIdx.x >> 5;
    if ((threadIdx.x & 31) == 0) { smin[w] = lmin; smax[w] = lmax; ss2[w] = s2; }
    __syncthreads();
    if (threadIdx.x == 0) {
        double b2 = 0.0;
        for (int i = 0; i < (int)(blockDim.x >> 5); i++) {
            lmin = fminf(lmin, smin[i]);
            lmax = fmaxf(lmax, smax[i]);
            b2 += ss2[i];
        }
        atomicMin(&g_min_enc, enc_f(lmin));
        atomicMax(&g_max_enc, enc_f(lmax));
        g_s2blk[blockIdx.x] = b2;
    }
}

__global__ void __launch_bounds__(512) cand_kernel() {
    __shared__ double sd[512];
    int t = threadIdx.x;
    sd[t] = g_s2blk[t];           // MMGRID == 512
    __syncthreads();
    for (int off = 256; off; off >>= 1) {
        if (t < off) sd[t] += sd[t + off];
        __syncthreads();
    }
    const float x_min = dec_f(g_min_enc);
    const float x_max = dec_f(g_max_enc);
    const float xrange = x_max - x_min;
    if (t == 0) {
        g_S2tot = sd[0];
        g_xminf = x_min;
        g_invwf = (float)NB / xrange;
        double wbin = (double)xrange / (double)NB;
        g_W36 = llrint(wbin * FIXS);
    }
    const float EPS = 1.1920929e-7f;
    for (int c = t; c < NCAND; c += 512) {
        int i = c / NZ + 1;
        int z = c % NZ;
        float fi = (float)i, fz = (float)z;
        float tmp_max   = xrange / 100.0f * fi;
        float tmp_delta = tmp_max / 15.0f;
        float new_min = fmaxf(-fz * tmp_delta, x_min);
        float new_max = fminf(tmp_max - fz * tmp_delta, x_max);
        float min_neg = fminf(new_min, 0.0f);
        float max_pos = fmaxf(new_max, 0.0f);
        float scale = fmaxf((max_pos - min_neg) / 15.0f, EPS);
        float zp = fminf(fmaxf(0.0f - rintf(min_neg / scale), 0.0f), 15.0f);
        g_sc[c] = scale;
        g_ql[c] = -zp;
        g_newmin[c] = new_min;
        g_newmax[c] = new_max;
    }
}

// histogram: ONE u64 atomic per element (was u32 + u64)
__global__ void hist_kernel(const float4* __restrict__ x4, int n4) {
    const float xminf = g_xminf;
    const float invwf = g_invwf;
    const s64   W36   = g_W36;
    for (int i = blockIdx.x * blockDim.x + threadIdx.x; i < n4;
         i += gridDim.x * blockDim.x) {
        float4 v = x4[i];
        float f[4] = {v.x, v.y, v.z, v.w};
        #pragma unroll
        for (int k = 0; k < 4; k++) {
            float d = f[k] - xminf;
            int b = (int)(d * invwf);
            b = min(max(b, 0), NB - 1);
            double dd = (double)f[k] - (double)xminf;   // exact
            s64 fx = llrint(dd * FIXS);
            u64 val = (1ull << CNT_SHIFT) + (u64)(fx - (s64)b * W36 + BIASI);
            atomicAdd(&g_hist[b], val);
        }
    }
}

__global__ void chunkred_kernel() {
    __shared__ u32 sc[256];
    __shared__ u64 ss[256];
    int b = blockIdx.x, t = threadIdx.x;
    const s64 W36 = g_W36;
    u32 c = 0; u64 s = 0;
    for (int j = t; j < CHUNK; j += 256) {
        int bin = b * CHUNK + j;
        u64 p = g_hist[bin];
        u32 cnt = (u32)(p >> CNT_SHIFT);
        s64 adj = (s64)(p & SUM_MASK) + (s64)cnt * ((s64)bin * W36 - BIASI);
        c += cnt; s += (u64)adj;
    }
    sc[t] = c; ss[t] = s; __syncthreads();
    for (int off = 128; off; off >>= 1) {
        if (t < off) { sc[t] += sc[t + off]; ss[t] += ss[t + off]; }
        __syncthreads();
    }
    if (t == 0) { g_ccnt[b] = sc[0]; g_csum[b] = ss[0]; }
}

__global__ void __launch_bounds__(NCHUNK) chunkscan_kernel() {
    __shared__ u32 sc[NCHUNK];
    __shared__ u64 ss[NCHUNK];
    int t = threadIdx.x;
    u32 v = g_ccnt[t];
    u64 w = g_csum[t];
    sc[t] = v; ss[t] = w; __syncthreads();
    for (int off = 1; off < NCHUNK; off <<= 1) {
        u32 a = 0; u64 a2 = 0;
        if (t >= off) { a = sc[t - off]; a2 = ss[t - off]; }
        __syncthreads();
        sc[t] += a; ss[t] += a2;
        __syncthreads();
    }
    g_ccnt[t] = sc[t] - v;   // exclusive
    g_csum[t] = ss[t] - w;
}

__global__ void __launch_bounds__(CHUNK) binscan_kernel() {
    __shared__ u32 sc[CHUNK];
    __shared__ u64 ss[CHUNK];
    int b = blockIdx.x, t = threadIdx.x;
    const s64 W36 = g_W36;
    int i = b * CHUNK + t;
    u64 p = g_hist[i];
    u32 v = (u32)(p >> CNT_SHIFT);
    u64 w = (u64)((s64)(p & SUM_MASK) + (s64)v * ((s64)i * W36 - BIASI));
    sc[t] = v; ss[t] = w; __syncthreads();
    for (int off = 1; off < CHUNK; off <<= 1) {
        u32 a = 0; u64 a2 = 0;
        if (t >= off) { a = sc[t - off]; a2 = ss[t - off]; }
        __syncthreads();
        sc[t] += a; ss[t] += a2;
        __syncthreads();
    }
    g_pc[i] = g_ccnt[b] + (sc[t] - v);
    g_ps[i] = g_csum[b] + (ss[t] - w);
    if (i == NB - 1) {
        g_pc[NB] = g_ccnt[b] + sc[t];
        g_ps[NB] = g_csum[b] + ss[t];
    }
}

__device__ __forceinline__ int gidx(float E, float xminf, float invwf) {
    float t = (E - xminf) * invwf;
    if (!(t > 0.0f)) return 0;
    if (t >= (float)NB) return NB;
    return (int)t;
}

__global__ void assemble_kernel(int ntot) {
    int c = blockIdx.x * blockDim.x + threadIdx.x;
    if (c >= NCAND) return;
    const float xminf = g_xminf;
    const float invwf = g_invwf;
    const double xmind = (double)xminf;
    float s  = g_sc[c];
    float ql = g_ql[c];
    int e[NZ + 1];
    e[0] = 0; e[NZ] = NB;
    #pragma unroll
    for (int m = 0; m < NZ - 1; m++)
        e[m + 1] = gidx((ql + (float)m + 0.5f) * s, xminf, invwf);
    #pragma unroll
    for (int m = 1; m < NZ; m++) if (e[m] < e[m - 1]) e[m] = e[m - 1];
    double num = 0.0;
    #pragma unroll
    for (int m = 0; m < NZ; m++) {
        u32 pc0 = g_pc[e[m]],  pc1 = g_pc[e[m + 1]];
        u64 ps0 = g_ps[e[m]],  ps1 = g_ps[e[m + 1]];
        double Nm = (double)(pc1 - pc0);
        double S1 = (double)(long long)(ps1 - ps0) * INVFIXS + Nm * xmind;
        float a = (ql + (float)m) * s;
        double ad = (double)a;
        num += ad * ad * Nm - 2.0 * ad * S1;
    }
    g_score[c] = (num + g_S2tot) / (double)ntot;
}

__global__ void __launch_bounds__(128) select_kernel(float* __restrict__ out) {
    __shared__ double sm_i[NITER];
    __shared__ int    j_i[NITER];
    int t = threadIdx.x;
    if (t < NITER) {
        int j = 0;
        double sm = g_score[t * NZ];
        #pragma unroll
        for (int z = 1; z < NZ; z++) {
            double s = g_score[t * NZ + z];
            if (s < sm) { sm = s; j = z; }
        }
        sm_i[t] = sm; j_i[t] = j;
    }
    __syncthreads();
    if (t == 0) {
        double best = 1e30;
        float bmin = dec_f(g_min_enc);
        float bmax = dec_f(g_max_enc);
        for (int i = 0; i < NITER; i++) {
            if (sm_i[i] < best) {
                best = sm_i[i];
                bmin = g_newmin[i * NZ + j_i[i]];
                bmax = g_newmax[i * NZ + j_i[i]];
            }
        }
        out[0] = bmin;
        out[1] = bmax;
    }
}

extern "C" void kernel_launch(void* const* d_in, const int* in_sizes, int n_in,
                              void* d_out, int out_size) {
    const float* x = (const float*)d_in[0];
    int n = in_sizes[0];
    int n4 = n / 4;

    clear_kernel<<<NB / 1024, 1024>>>();
    minmax_s2_kernel<<<MMGRID, 256>>>((const float4*)x, n4);
    cand_kernel<<<1, 512>>>();
    hist_kernel<<<2048, 256>>>((const float4*)x, n4);
    chunkred_kernel<<<NCHUNK, 256>>>();
    chunkscan_kernel<<<1, NCHUNK>>>();
    binscan_kernel<<<NCHUNK, CHUNK>>>();
    assemble_kernel<<<(NCAND + 127) / 128, 128>>>(n);
    select_kernel<<<1, 128>>>((float*)d_out);
}

// round 15
// speedup vs baseline: 2.2265x; 1.4878x over previous
#include <cuda_runtime.h>
#include <stdint.h>

#define NCAND  1600
#define NITER  100
#define NZ     16
#define NB     524288          // histogram bins (2^19)
#define FRAC   4               // sub-bin bits; NB<<FRAC = 2^23
#define CHUNK  1024
#define NCHUNK (NB / CHUNK)    // 512
#define MMGRID 512

typedef unsigned long long u64;
typedef long long          s64;
typedef unsigned u32;

#define MAGICF 8388608.0f      // 2^23
#define HIF    16777215.0f     // 2^24 - 1
#define OVF    16777216.0f     // 2^24

__device__ u32    g_min_enc;
__device__ u32    g_max_enc;
__device__ float  g_xminf;
__device__ float  g_xrange;
__device__ float  g_C1, g_C2;
__device__ float  g_sc[NCAND];
__device__ float  g_ql[NCAND];
__device__ float  g_newmin[NCAND];
__device__ float  g_newmax[NCAND];
__device__ double g_score[NCAND];
__device__ u64    g_hist[NB];   // (count << 32) | sum_of_4bit_offsets
__device__ u32    g_pc[NB + 1];
__device__ u64    g_ps[NB + 1];
__device__ u32    g_ccnt[NCHUNK];
__device__ u64    g_csum[NCHUNK];

__device__ __forceinline__ u32 enc_f(float f) {
    u32 u = __float_as_uint(f);
    return (u & 0x80000000u) ? ~u : (u | 0x80000000u);
}
__device__ __forceinline__ float dec_f(u32 e) {
    return (e & 0x80000000u) ? __uint_as_float(e & 0x7fffffffu)
                             : __uint_as_float(~e);
}

__global__ void clear_kernel() {
    int i = blockIdx.x * blockDim.x + threadIdx.x;
    if (i < NB) g_hist[i] = 0ull;
    if (i == 0) { g_min_enc = 0xFFFFFFFFu; g_max_enc = 0u; }
}

// pass A: per-block min/max (FP64 Σx² removed — constant offset, cancels)
__global__ void minmax_s2_kernel(const float4* __restrict__ x4, int n4) {
    float lmin = 3.4e38f, lmax = -3.4e38f;
    for (int i = blockIdx.x * blockDim.x + threadIdx.x; i < n4;
         i += gridDim.x * blockDim.x) {
        float4 v = x4[i];
        lmin = fminf(lmin, fminf(fminf(v.x, v.y), fminf(v.z, v.w)));
        lmax = fmaxf(lmax, fmaxf(fmaxf(v.x, v.y), fmaxf(v.z, v.w)));
    }
    #pragma unroll
    for (int o = 16; o; o >>= 1) {
        lmin = fminf(lmin, __shfl_xor_sync(0xffffffffu, lmin, o));
        lmax = fmaxf(lmax, __shfl_xor_sync(0xffffffffu, lmax, o));
    }
    __shared__ float smin[8], smax[8];
    int w = threadIdx.x >> 5;
    if ((threadIdx.x & 31) == 0) { smin[w] = lmin; smax[w] = lmax; }
    __syncthreads();
    if (threadIdx.x == 0) {
        for (int i = 1; i < (int)(blockDim.x >> 5); i++) {
            lmin = fminf(lmin, smin[i]);
            lmax = fmaxf(lmax, smax[i]);
        }
        atomicMin(&g_min_enc, enc_f(lmin));
        atomicMax(&g_max_enc, enc_f(lmax));
    }
}

__global__ void __launch_bounds__(512) cand_kernel() {
    int t = threadIdx.x;
    const float x_min = dec_f(g_min_enc);
    const float x_max = dec_f(g_max_enc);
    const float xrange = x_max - x_min;
    if (t == 0) {
        float C1 = MAGICF / xrange;
        g_xminf  = x_min;
        g_xrange = xrange;
        g_C1 = C1;
        g_C2 = MAGICF - x_min * C1;
    }
    const float EPS = 1.1920929e-7f;
    for (int c = t; c < NCAND; c += 512) {
        int i = c / NZ + 1;
        int z = c % NZ;
        float fi = (float)i, fz = (float)z;
        float tmp_max   = xrange / 100.0f * fi;
        float tmp_delta = tmp_max / 15.0f;
        float new_min = fmaxf(-fz * tmp_delta, x_min);
        float new_max = fminf(tmp_max - fz * tmp_delta, x_max);
        float min_neg = fminf(new_min, 0.0f);
        float max_pos = fmaxf(new_max, 0.0f);
        float scale = fmaxf((max_pos - min_neg) / 15.0f, EPS);
        float zp = fminf(fmaxf(0.0f - rintf(min_neg / scale), 0.0f), 15.0f);
        g_sc[c] = scale;
        g_ql[c] = -zp;
        g_newmin[c] = new_min;
        g_newmax[c] = new_max;
    }
}

// histogram: magic-constant binning (f32 only), ONE u64 atomic per element
__global__ void hist_kernel(const float4* __restrict__ x4, int n4) {
    const float C1 = g_C1;
    const float C2 = g_C2;
    for (int i = blockIdx.x * blockDim.x + threadIdx.x; i < n4;
         i += gridDim.x * blockDim.x) {
        float4 v = x4[i];
        float f[4] = {v.x, v.y, v.z, v.w};
        #pragma unroll
        for (int k = 0; k < 4; k++) {
            float t = fminf(fmaxf(fmaf(f[k], C1, C2), MAGICF), HIF);
            u32 q = __float_as_uint(t) - 0x4B000000u;     // 23-bit position
            atomicAdd(&g_hist[q >> FRAC],
                      (1ull << 32) + (u64)(q & ((1u << FRAC) - 1u)));
        }
    }
}

__global__ void chunkred_kernel() {
    __shared__ u32 sc[256];
    __shared__ u64 ss[256];
    int b = blockIdx.x, t = threadIdx.x;
    u32 c = 0; u64 s = 0;
    for (int j = t; j < CHUNK; j += 256) {
        int bin = b * CHUNK + j;
        u64 p = g_hist[bin];
        u32 cnt = (u32)(p >> 32);
        s += ((u64)cnt * (u64)bin << FRAC) + (p & 0xFFFFFFFFull);
        c += cnt;
    }
    sc[t] = c; ss[t] = s; __syncthreads();
    for (int off = 128; off; off >>= 1) {
        if (t < off) { sc[t] += sc[t + off]; ss[t] += ss[t + off]; }
        __syncthreads();
    }
    if (t == 0) { g_ccnt[b] = sc[0]; g_csum[b] = ss[0]; }
}

__global__ void __launch_bounds__(NCHUNK) chunkscan_kernel() {
    __shared__ u32 sc[NCHUNK];
    __shared__ u64 ss[NCHUNK];
    int t = threadIdx.x;
    u32 v = g_ccnt[t];
    u64 w = g_csum[t];
    sc[t] = v; ss[t] = w; __syncthreads();
    for (int off = 1; off < NCHUNK; off <<= 1) {
        u32 a = 0; u64 a2 = 0;
        if (t >= off) { a = sc[t - off]; a2 = ss[t - off]; }
        __syncthreads();
        sc[t] += a; ss[t] += a2;
        __syncthreads();
    }
    g_ccnt[t] = sc[t] - v;   // exclusive
    g_csum[t] = ss[t] - w;
}

__global__ void __launch_bounds__(CHUNK) binscan_kernel() {
    __shared__ u32 sc[CHUNK];
    __shared__ u64 ss[CHUNK];
    int b = blockIdx.x, t = threadIdx.x;
    int i = b * CHUNK + t;
    u64 p = g_hist[i];
    u32 v = (u32)(p >> 32);
    u64 w = ((u64)v * (u64)i << FRAC) + (p & 0xFFFFFFFFull);
    sc[t] = v; ss[t] = w; __syncthreads();
    for (int off = 1; off < CHUNK; off <<= 1) {
        u32 a = 0; u64 a2 = 0;
        if (t >= off) { a = sc[t - off]; a2 = ss[t - off]; }
        __syncthreads();
        sc[t] += a; ss[t] += a2;
        __syncthreads();
    }
    g_pc[i] = g_ccnt[b] + (sc[t] - v);
    g_ps[i] = g_csum[b] + (ss[t] - w);
    if (i == NB - 1) {
        g_pc[NB] = g_ccnt[b] + sc[t];
        g_ps[NB] = g_csum[b] + ss[t];
    }
}

__global__ void assemble_kernel(int ntot) {
    int c = blockIdx.x * blockDim.x + threadIdx.x;
    if (c >= NCAND) return;
    const float C1 = g_C1;
    const float C2 = g_C2;
    const double xmind = (double)g_xminf;
    const double UPQ = (double)g_xrange / (double)(1 << 23);  // x per q-unit
    float s  = g_sc[c];
    float ql = g_ql[c];
    int e[NZ + 1];
    e[0] = 0; e[NZ] = NB;
    #pragma unroll
    for (int m = 0; m < NZ - 1; m++) {
        float tr = fmaf((ql + (float)m + 0.5f) * s, C1, C2);
        int ei;
        if (!(tr > MAGICF))      ei = 0;
        else if (tr >= OVF)      ei = NB;
        else ei = (int)((__float_as_uint(tr) - 0x4B000000u) >> FRAC);
        e[m + 1] = ei;
    }
    #pragma unroll
    for (int m = 1; m < NZ; m++) if (e[m] < e[m - 1]) e[m] = e[m - 1];
    double num = 0.0;
    #pragma unroll
    for (int m = 0; m < NZ; m++) {
        u32 pc0 = g_pc[e[m]],  pc1 = g_pc[e[m + 1]];
        u64 ps0 = g_ps[e[m]],  ps1 = g_ps[e[m + 1]];
        double Nm = (double)(pc1 - pc0);
        double S1 = (double)(long long)(ps1 - ps0) * UPQ + Nm * xmind;
        float a = (ql + (float)m) * s;
        double ad = (double)a;
        num += ad * ad * Nm - 2.0 * ad * S1;
    }
    g_score[c] = num / (double)ntot;    // Σx² omitted: constant offset
}

__global__ void __launch_bounds__(128) select_kernel(float* __restrict__ out) {
    __shared__ double sm_i[NITER];
    __shared__ int    j_i[NITER];
    int t = threadIdx.x;
    if (t < NITER) {
        int j = 0;
        double sm = g_score[t * NZ];
        #pragma unroll
        for (int z = 1; z < NZ; z++) {
            double s = g_score[t * NZ + z];
            if (s < sm) { sm = s; j = z; }
        }
        sm_i[t] = sm; j_i[t] = j;
    }
    __syncthreads();
    if (t == 0) {
        double best = 1e30;
        float bmin = dec_f(g_min_enc);
        float bmax = dec_f(g_max_enc);
        for (int i = 0; i < NITER; i++) {
            if (sm_i[i] < best) {
                best = sm_i[i];
                bmin = g_newmin[i * NZ + j_i[i]];
                bmax = g_newmax[i * NZ + j_i[i]];
            }
        }
        out[0] = bmin;
        out[1] = bmax;
    }
}

extern "C" void kernel_launch(void* const* d_in, const int* in_sizes, int n_in,
                              void* d_out, int out_size) {
    const float* x = (const float*)d_in[0];
    int n = in_sizes[0];
    int n4 = n / 4;

    clear_kernel<<<NB / 1024, 1024>>>();
    minmax_s2_kernel<<<MMGRID, 256>>>((const float4*)x, n4);
    cand_kernel<<<1, 512>>>();
    hist_kernel<<<2048, 256>>>((const float4*)x, n4);
    chunkred_kernel<<<NCHUNK, 256>>>();
    chunkscan_kernel<<<1, NCHUNK>>>();
    binscan_kernel<<<NCHUNK, CHUNK>>>();
    assemble_kernel<<<(NCAND + 127) / 128, 128>>>(n);
    select_kernel<<<1, 128>>>((float*)d_out);
}